// round 8
// baseline (speedup 1.0000x reference)
#include <cuda_runtime.h>
#include <math.h>

#define B_   32
#define T_   64
#define BT   2048            // B*T
#define IND  4894
#define E_   128
#define G3   384             // 3*H
#define NG   768             // both GRUs' gates

#define KC   36              // kk rows of Whh cached in smem
#define WST  36              // smem stride in floats (144B, 16B-aligned, conflict-free)
#define SMEM_DYN_FLOATS (E_*E_ + 768*WST)   // 16384 + 27648 = 44032
#define SMEM_DYN_BYTES  (SMEM_DYN_FLOATS * 4)  // 176128

// ---------------- device scratch (no allocations allowed) ----------------
__device__ float g_emb[BT * E_];       // emb[m][e]  (atomicAdd target)
__device__ float g_GI [BT * NG];       // input gates + bih (+ bhh for r,z)
__device__ float g_Wbeta2[E_ * E_];    // [kk][ (e&31)*4 + (e>>5) ]

__device__ __forceinline__ float fast_tanh(float x) {
    float y; asm("tanh.approx.f32 %0, %1;" : "=f"(y) : "f"(x)); return y;
}
__device__ __forceinline__ float fast_sigmoid(float x) {
    return 0.5f * fast_tanh(0.5f * x) + 0.5f;
}

// ---------------- K0: prep — W_beta interleave + zero g_emb ----------------
__global__ void k_prep(const float* __restrict__ W_beta) {
    int idx = blockIdx.x * 256 + threadIdx.x;
    if (idx < E_ * E_) {
        int kk = idx >> 7, e = idx & 127;
        g_Wbeta2[kk * 128 + ((e & 31) << 2) + (e >> 5)] = W_beta[e * E_ + kk];
    } else {
        int z = idx - E_ * E_;
        if (z < BT * E_) g_emb[z] = 0.f;
    }
}

// ---------------- K1: embedding GEMM  emb += x @ W_emb^T (2-way split-K) ----
// grid (64, 2), 256 threads. BM=32, BN=128, thread tile 4m x 4n.
__global__ void __launch_bounds__(256) k_embed(const float* __restrict__ x,
                                               const float* __restrict__ Wemb) {
    __shared__ float As[32][36];    // [kk][m]
    __shared__ float Bs[32][132];   // [kk][e]
    const int m0   = blockIdx.x * 32;
    const int kbeg = blockIdx.y * 2448;
    const int kend = (kbeg + 2448 < IND) ? (kbeg + 2448) : IND;
    const int tid  = threadIdx.x;
    const int tx   = tid & 31;      // n = tx*4 + b
    const int ty   = tid >> 5;      // m = ty*4 + a
    float acc[4][4];
#pragma unroll
    for (int a = 0; a < 4; a++)
#pragma unroll
        for (int b = 0; b < 4; b++) acc[a][b] = 0.f;

    for (int k0 = kbeg; k0 < kend; k0 += 32) {
        for (int l = tid; l < 32 * 32; l += 256) {
            int kk = l & 31, mm = l >> 5;
            int k = k0 + kk;
            As[kk][mm] = (k < kend) ? x[(m0 + mm) * IND + k] : 0.f;
        }
        for (int l = tid; l < 128 * 32; l += 256) {
            int kk = l & 31, ee = l >> 5;
            int k = k0 + kk;
            Bs[kk][ee] = (k < kend) ? Wemb[ee * IND + k] : 0.f;
        }
        __syncthreads();
#pragma unroll
        for (int kk = 0; kk < 32; kk++) {
            float4 av = *(const float4*)&As[kk][ty * 4];
            float4 bv = *(const float4*)&Bs[kk][tx * 4];
            float am[4] = {av.x, av.y, av.z, av.w};
            float bn[4] = {bv.x, bv.y, bv.z, bv.w};
#pragma unroll
            for (int a = 0; a < 4; a++)
#pragma unroll
                for (int b = 0; b < 4; b++) acc[a][b] += am[a] * bn[b];
        }
        __syncthreads();
    }
#pragma unroll
    for (int a = 0; a < 4; a++)
#pragma unroll
        for (int b = 0; b < 4; b++)
            atomicAdd(&g_emb[(m0 + ty * 4 + a) * E_ + tx * 4 + b], acc[a][b]);
}

// ---------------- K3: GI = temb @ [Wih_a | Wih_b]^T + bih (+bhh for r,z) ----
__global__ void __launch_bounds__(256) k_gi(const float* __restrict__ tt,
                                            const float* __restrict__ Wih_a,
                                            const float* __restrict__ Wih_b,
                                            const float* __restrict__ bih_a,
                                            const float* __restrict__ bih_b,
                                            const float* __restrict__ bhh_a,
                                            const float* __restrict__ bhh_b) {
    __shared__ float As[64][33];
    __shared__ float Bs[64][68];
    const int m0  = blockIdx.x * 32;
    const int n0  = blockIdx.y * 64;
    const int tid = threadIdx.x;
    const int tx  = tid & 15;
    const int ty  = tid >> 4;
    float acc[2][4];
#pragma unroll
    for (int a = 0; a < 2; a++)
#pragma unroll
        for (int b = 0; b < 4; b++) acc[a][b] = 0.f;

    for (int k0 = 0; k0 < 129; k0 += 64) {
        for (int l = tid; l < 64 * 32; l += 256) {
            int kk = l & 63, mm = l >> 6;
            int k = k0 + kk;
            float v = 0.f;
            if (k < 128)       v = g_emb[(m0 + mm) * E_ + k];
            else if (k == 128) v = tt[m0 + mm];
            As[kk][mm] = v;
        }
        for (int l = tid; l < 64 * 64; l += 256) {
            int kk = l & 63, e = l >> 6;
            int k = k0 + kk;
            int g = n0 + e;
            float v = 0.f;
            if (k < 129)
                v = (g < G3) ? Wih_a[g * 129 + k] : Wih_b[(g - G3) * 129 + k];
            Bs[kk][e] = v;
        }
        __syncthreads();
#pragma unroll 8
        for (int kk = 0; kk < 64; kk++) {
            float a0 = As[kk][ty * 2];
            float a1 = As[kk][ty * 2 + 1];
            float4 bv = *(const float4*)&Bs[kk][tx * 4];
            acc[0][0] += a0 * bv.x; acc[0][1] += a0 * bv.y;
            acc[0][2] += a0 * bv.z; acc[0][3] += a0 * bv.w;
            acc[1][0] += a1 * bv.x; acc[1][1] += a1 * bv.y;
            acc[1][2] += a1 * bv.z; acc[1][3] += a1 * bv.w;
        }
        __syncthreads();
    }
#pragma unroll
    for (int a = 0; a < 2; a++)
#pragma unroll
        for (int b = 0; b < 4; b++) {
            int g  = n0 + tx * 4 + b;
            int gg = (g < G3) ? g : g - G3;
            float bias = (g < G3) ? bih_a[gg] : bih_b[gg];
            if (gg < 256)                          // r,z: fold bhh too
                bias += (g < G3) ? bhh_a[gg] : bhh_b[gg];
            g_GI[(m0 + ty * 2 + a) * NG + g] = acc[a][b] + bias;
        }
}

// ---------------- K4: fused GRU recurrence + online-softmax attention --------
// 128 blocks x 512 threads. Two independent 256-thread teams per CTA run the
// paired sequences {63-p, p} CONCURRENTLY (named barriers per team).
__global__ void __launch_bounds__(512, 1)
k_main(const int*   __restrict__ lengths,
       const float* __restrict__ Whh_a,
       const float* __restrict__ Whh_b,
       const float* __restrict__ bhh_a,
       const float* __restrict__ bhh_b,
       const float* __restrict__ w_alpha,
       const float* __restrict__ b_alpha,
       const float* __restrict__ b_beta,
       const float* __restrict__ W_out,
       const float* __restrict__ b_out,
       float* __restrict__ out) {
    extern __shared__ float dynsm[];
    float* ws_beta = dynsm;                 // [kk][lane*4+q]  16384 floats
    float* ws_whh  = dynsm + E_ * E_;       // [col][kk<KC], stride WST

    __shared__ float sh_h[2][2][2][E_][8];  // [team][buf][gru][e][row]  32KB
    __shared__ float sh_wal[E_], sh_bbe[E_], sh_wout[E_];
    __shared__ float sh_balpha, sh_bout;

    const int tid   = threadIdx.x;
    const int team  = tid >> 8;
    const int ttid  = tid & 255;
    const int gru   = ttid >> 7;            // 0 = GRU-a, 1 = GRU-b
    const int e     = ttid & 127;
    const int row   = ttid >> 5;            // 0..7 within team
    const int lane  = tid & 31;
    const int pairp = blockIdx.x >> 2;      // 0..31
    const int bo    = blockIdx.x & 3;
    const int bb    = bo * 8 + row;
    const int i     = team ? pairp : (63 - pairp);
    const int cr    = gru * G3 + e;

    // prologue: weight caches + consts (all 512 threads)
    for (int l = tid; l < E_ * E_ / 4; l += 512)
        ((float4*)ws_beta)[l] = ((const float4*)g_Wbeta2)[l];
    for (int l = tid; l < 768 * KC; l += 512) {
        int col = l / KC, kk = l - col * KC;
        ws_whh[col * WST + kk] = (col < G3) ? Whh_a[col * E_ + kk]
                                            : Whh_b[(col - G3) * E_ + kk];
    }
    if (tid < E_) {
        sh_wal[tid]  = w_alpha[tid];
        sh_bbe[tid]  = b_beta[tid];
        sh_wout[tid] = W_out[tid];
    }
    if (tid == 0) { sh_balpha = b_alpha[0]; sh_bout = b_out[0]; }
    __syncthreads();

    const float* __restrict__ wsrc = gru ? Whh_b : Whh_a;   // [384][128] row-major
    const float bhhn = (gru ? bhh_b : bhh_a)[256 + e];

    // zero this team's "prev" buffer (buf 1; k=0 has cur=0)
    {
        float* hz = &sh_h[team][1][0][0][0];
        for (int l = ttid; l < 2 * E_ * 8; l += 256) hz[l] = 0.f;
    }
    float m_run = -INFINITY, d_run = 0.f;
    float c0 = 0.f, c1 = 0.f, c2 = 0.f, c3 = 0.f;
    asm volatile("bar.sync %0, 256;" :: "r"(team + 1) : "memory");

    for (int k = 0; k <= i; k++) {
        const int j    = i - k;
        const int cur  = k & 1;
        const int prev = cur ^ 1;
        const float* hp = &sh_h[team][prev][gru][0][0];     // [kk*8 + row]

        // r/z accumulators start at precomputed GI (bih+bhh folded);
        // n accumulator starts at 0 (gin applied inside tanh with r-mult)
        float aR[8], aZ[8], aN[8], gin[8];
        {
            const float* gp0 = g_GI + (bo * 8 * T_ + j) * NG + cr;
#pragma unroll
            for (int r = 0; r < 8; r++) {
                const float* gp = gp0 + r * (T_ * NG);
                aR[r] = gp[0]; aZ[r] = gp[128]; gin[r] = gp[256]; aN[r] = 0.f;
            }
        }

        // gh GEMM, smem-cached kk < KC
#pragma unroll
        for (int kk = 0; kk < KC; kk += 4) {
            float4 wr4 = *(const float4*)&ws_whh[cr * WST + kk];
            float4 wz4 = *(const float4*)&ws_whh[(cr + 128) * WST + kk];
            float4 wn4 = *(const float4*)&ws_whh[(cr + 256) * WST + kk];
            const float* wr = (const float*)&wr4;
            const float* wz = (const float*)&wz4;
            const float* wn = (const float*)&wn4;
#pragma unroll
            for (int s = 0; s < 4; s++) {
                float4 h0 = *(const float4*)(hp + (kk + s) * 8);
                float4 h1 = *(const float4*)(hp + (kk + s) * 8 + 4);
                float r0 = wr[s], z0 = wz[s], n0 = wn[s];
                aR[0] += r0 * h0.x; aR[1] += r0 * h0.y; aR[2] += r0 * h0.z; aR[3] += r0 * h0.w;
                aR[4] += r0 * h1.x; aR[5] += r0 * h1.y; aR[6] += r0 * h1.z; aR[7] += r0 * h1.w;
                aZ[0] += z0 * h0.x; aZ[1] += z0 * h0.y; aZ[2] += z0 * h0.z; aZ[3] += z0 * h0.w;
                aZ[4] += z0 * h1.x; aZ[5] += z0 * h1.y; aZ[6] += z0 * h1.z; aZ[7] += z0 * h1.w;
                aN[0] += n0 * h0.x; aN[1] += n0 * h0.y; aN[2] += n0 * h0.z; aN[3] += n0 * h0.w;
                aN[4] += n0 * h1.x; aN[5] += n0 * h1.y; aN[6] += n0 * h1.z; aN[7] += n0 * h1.w;
            }
        }
        // gh GEMM, L2-streamed kk >= KC (row-major Whh: float4 along kk)
#pragma unroll 2
        for (int kk = KC; kk < E_; kk += 4) {
            float4 wr4 = *(const float4*)&wsrc[e * E_ + kk];
            float4 wz4 = *(const float4*)&wsrc[(e + 128) * E_ + kk];
            float4 wn4 = *(const float4*)&wsrc[(e + 256) * E_ + kk];
            const float* wr = (const float*)&wr4;
            const float* wz = (const float*)&wz4;
            const float* wn = (const float*)&wn4;
#pragma unroll
            for (int s = 0; s < 4; s++) {
                float4 h0 = *(const float4*)(hp + (kk + s) * 8);
                float4 h1 = *(const float4*)(hp + (kk + s) * 8 + 4);
                float r0 = wr[s], z0 = wz[s], n0 = wn[s];
                aR[0] += r0 * h0.x; aR[1] += r0 * h0.y; aR[2] += r0 * h0.z; aR[3] += r0 * h0.w;
                aR[4] += r0 * h1.x; aR[5] += r0 * h1.y; aR[6] += r0 * h1.z; aR[7] += r0 * h1.w;
                aZ[0] += z0 * h0.x; aZ[1] += z0 * h0.y; aZ[2] += z0 * h0.z; aZ[3] += z0 * h0.w;
                aZ[4] += z0 * h1.x; aZ[5] += z0 * h1.y; aZ[6] += z0 * h1.z; aZ[7] += z0 * h1.w;
                aN[0] += n0 * h0.x; aN[1] += n0 * h0.y; aN[2] += n0 * h0.z; aN[3] += n0 * h0.w;
                aN[4] += n0 * h1.x; aN[5] += n0 * h1.y; aN[6] += n0 * h1.z; aN[7] += n0 * h1.w;
            }
        }

        // gate combine in registers; write h_new into cur buffer
        {
            const float* hold = &sh_h[team][prev][gru][e][0];
            float4 ho0 = *(const float4*)(hold);
            float4 ho1 = *(const float4*)(hold + 4);
            float holda[8] = {ho0.x, ho0.y, ho0.z, ho0.w, ho1.x, ho1.y, ho1.z, ho1.w};
            float hn[8];
#pragma unroll
            for (int r = 0; r < 8; r++) {
                float rg = fast_sigmoid(aR[r]);              // bhh_r folded in GI
                float zg = fast_sigmoid(aZ[r]);              // bhh_z folded in GI
                float ng = fast_tanh(gin[r] + rg * (aN[r] + bhhn));
                hn[r] = (1.f - zg) * ng + zg * holda[r];
            }
            float* hw = &sh_h[team][cur][gru][e][0];
            *(float4*)hw       = make_float4(hn[0], hn[1], hn[2], hn[3]);
            *(float4*)(hw + 4) = make_float4(hn[4], hn[5], hn[6], hn[7]);
        }
        asm volatile("bar.sync %0, 256;" :: "r"(team + 1) : "memory");

        // phase D (warp = row): score, online softmax, beta, numerator
        {
            float p = 0.f;
#pragma unroll
            for (int q = 0; q < 4; q++)
                p += sh_h[team][cur][0][lane + 32 * q][row] * sh_wal[lane + 32 * q];
            p += __shfl_xor_sync(0xffffffffu, p, 16);
            p += __shfl_xor_sync(0xffffffffu, p, 8);
            p += __shfl_xor_sync(0xffffffffu, p, 4);
            p += __shfl_xor_sync(0xffffffffu, p, 2);
            p += __shfl_xor_sync(0xffffffffu, p, 1);
            float s  = p + sh_balpha;
            float mn = fmaxf(m_run, s);
            float sc = __expf(m_run - mn);
            float w  = __expf(s - mn);
            d_run = d_run * sc + w;
            m_run = mn;

            float d0 = 0.f, d1 = 0.f, d2 = 0.f, d3 = 0.f;
            const float* hb = &sh_h[team][cur][1][0][row];
#pragma unroll 4
            for (int kk = 0; kk < E_; kk++) {
                float hv = hb[kk * 8];
                float4 wv = *(const float4*)&ws_beta[kk * 128 + (lane << 2)];
                d0 += hv * wv.x; d1 += hv * wv.y; d2 += hv * wv.z; d3 += hv * wv.w;
            }
            const float* ep = g_emb + (bb * T_ + j) * E_ + lane;
            c0 = c0 * sc + w * fast_tanh(d0 + sh_bbe[lane])      * ep[0];
            c1 = c1 * sc + w * fast_tanh(d1 + sh_bbe[lane + 32]) * ep[32];
            c2 = c2 * sc + w * fast_tanh(d2 + sh_bbe[lane + 64]) * ep[64];
            c3 = c3 * sc + w * fast_tanh(d3 + sh_bbe[lane + 96]) * ep[96];
        }
    }

    // epilogue per team
    {
        float inv_d = 1.f / d_run;
        float p = c0 * sh_wout[lane]      + c1 * sh_wout[lane + 32]
                + c2 * sh_wout[lane + 64] + c3 * sh_wout[lane + 96];
        p *= inv_d;
        p += __shfl_xor_sync(0xffffffffu, p, 16);
        p += __shfl_xor_sync(0xffffffffu, p, 8);
        p += __shfl_xor_sync(0xffffffffu, p, 4);
        p += __shfl_xor_sync(0xffffffffu, p, 2);
        p += __shfl_xor_sync(0xffffffffu, p, 1);
        if (lane == 0) {
            float valid = (i < lengths[bb]) ? 1.f : 0.f;
            out[bb * T_ + i] = p * valid + sh_bout;
        }
    }
}

// ---------------- launch ----------------
extern "C" void kernel_launch(void* const* d_in, const int* in_sizes, int n_in,
                              void* d_out, int out_size) {
    const float* x       = (const float*)d_in[0];
    const float* tt      = (const float*)d_in[1];
    const int*   lengths = (const int*)  d_in[2];
    const float* Wemb    = (const float*)d_in[3];
    const float* Wih_a   = (const float*)d_in[4];
    const float* Whh_a   = (const float*)d_in[5];
    const float* bih_a   = (const float*)d_in[6];
    const float* bhh_a   = (const float*)d_in[7];
    const float* Wih_b   = (const float*)d_in[8];
    const float* Whh_b   = (const float*)d_in[9];
    const float* bih_b   = (const float*)d_in[10];
    const float* bhh_b   = (const float*)d_in[11];
    const float* w_alpha = (const float*)d_in[12];
    const float* b_alpha = (const float*)d_in[13];
    const float* W_beta  = (const float*)d_in[14];
    const float* b_beta  = (const float*)d_in[15];
    const float* W_out   = (const float*)d_in[16];
    const float* b_out   = (const float*)d_in[17];
    float* out = (float*)d_out;

    cudaFuncSetAttribute(k_main, cudaFuncAttributeMaxDynamicSharedMemorySize,
                         SMEM_DYN_BYTES);

    k_prep<<<1088, 256>>>(W_beta);                         // beta layout + zero g_emb
    k_embed<<<dim3(64, 2), 256>>>(x, Wemb);                // split-K atomic GEMM
    k_gi<<<dim3(64, 12), 256>>>(tt, Wih_a, Wih_b, bih_a, bih_b, bhh_a, bhh_b);
    k_main<<<128, 512, SMEM_DYN_BYTES>>>(lengths, Whh_a, Whh_b, bhh_a, bhh_b,
                                         w_alpha, b_alpha, b_beta, W_out, b_out, out);
}

// round 9
// speedup vs baseline: 1.6850x; 1.6850x over previous
#include <cuda_runtime.h>
#include <math.h>

#define B_   32
#define T_   64
#define BT   2048            // B*T
#define IND  4894
#define E_   128
#define G3   384             // 3*H
#define NG   768             // both GRUs' gates
#define WPAD 132             // smem stride for Whh rows (conflict-free float4)
#define GRU_SMEM (G3 * WPAD * 4)   // 202752 B

// ---------------- device scratch (no allocations allowed) ----------------
__device__ float g_emb[BT * E_];        // emb[m][e]
__device__ float g_GI [BT * NG];        // input gates + bih (+ bhh for r,z)
__device__ float g_Wbeta2[E_ * E_];     // [kk][(e&31)*4 + (e>>5)]
__device__ float g_Hb[BT * T_ * E_];    // hb states, [b][i][k][e]  (64MB)
__device__ float g_S [BT * T_];         // attention scores [b][i][k]

__device__ __forceinline__ float fast_tanh(float x) {
    float y; asm("tanh.approx.f32 %0, %1;" : "=f"(y) : "f"(x)); return y;
}
__device__ __forceinline__ float fast_sigmoid(float x) {
    return 0.5f * fast_tanh(0.5f * x) + 0.5f;
}

// ---------------- K0: prep — W_beta interleave ----------------
__global__ void k_prep(const float* __restrict__ W_beta) {
    int idx = blockIdx.x * 256 + threadIdx.x;
    if (idx < E_ * E_) {
        int kk = idx >> 7, e = idx & 127;
        g_Wbeta2[kk * 128 + ((e & 31) << 2) + (e >> 5)] = W_beta[e * E_ + kk];
    }
}

// ---------------- K1: embedding GEMM  emb = x @ W_emb^T ----------------
// BM=16, 128 CTAs, 256 threads, 2m x 4n; register-prefetch double buffering.
__global__ void __launch_bounds__(256) k_embed(const float* __restrict__ x,
                                               const float* __restrict__ Wemb) {
    __shared__ float As[32][16];
    __shared__ float Bs[32][132];
    const int m0  = blockIdx.x * 16;
    const int tid = threadIdx.x;
    const int tx  = tid & 31;
    const int ty  = tid >> 5;
    float acc[2][4];
#pragma unroll
    for (int a = 0; a < 2; a++)
#pragma unroll
        for (int b = 0; b < 4; b++) acc[a][b] = 0.f;

    float pa[2], pb[16];
    // prefetch tile 0
    {
        int k0 = 0;
#pragma unroll
        for (int u = 0; u < 2; u++) {
            int l = tid + 256 * u, kk = l & 31, mm = l >> 5, k = k0 + kk;
            pa[u] = (k < IND) ? x[(m0 + mm) * IND + k] : 0.f;
        }
#pragma unroll
        for (int u = 0; u < 16; u++) {
            int l = tid + 256 * u, kk = l & 31, ee = l >> 5, k = k0 + kk;
            pb[u] = (k < IND) ? Wemb[ee * IND + k] : 0.f;
        }
    }
    for (int k0 = 0; k0 < IND; k0 += 32) {
        __syncthreads();    // previous compute done before overwriting smem
#pragma unroll
        for (int u = 0; u < 2; u++) {
            int l = tid + 256 * u;
            As[l & 31][l >> 5] = pa[u];
        }
#pragma unroll
        for (int u = 0; u < 16; u++) {
            int l = tid + 256 * u;
            Bs[l & 31][l >> 5] = pb[u];
        }
        __syncthreads();
        int kn = k0 + 32;
        if (kn < IND) {     // prefetch next tile (overlaps with compute)
#pragma unroll
            for (int u = 0; u < 2; u++) {
                int l = tid + 256 * u, kk = l & 31, mm = l >> 5, k = kn + kk;
                pa[u] = (k < IND) ? x[(m0 + mm) * IND + k] : 0.f;
            }
#pragma unroll
            for (int u = 0; u < 16; u++) {
                int l = tid + 256 * u, kk = l & 31, ee = l >> 5, k = kn + kk;
                pb[u] = (k < IND) ? Wemb[ee * IND + k] : 0.f;
            }
        }
#pragma unroll
        for (int kk = 0; kk < 32; kk++) {
            float a0 = As[kk][ty * 2];
            float a1 = As[kk][ty * 2 + 1];
            float4 bv = *(const float4*)&Bs[kk][tx * 4];
            acc[0][0] += a0 * bv.x; acc[0][1] += a0 * bv.y;
            acc[0][2] += a0 * bv.z; acc[0][3] += a0 * bv.w;
            acc[1][0] += a1 * bv.x; acc[1][1] += a1 * bv.y;
            acc[1][2] += a1 * bv.z; acc[1][3] += a1 * bv.w;
        }
    }
#pragma unroll
    for (int a = 0; a < 2; a++) {
        float4 v = make_float4(acc[a][0], acc[a][1], acc[a][2], acc[a][3]);
        *(float4*)&g_emb[(m0 + ty * 2 + a) * E_ + tx * 4] = v;
    }
}

// ---------------- K2: GI = temb @ [Wih_a | Wih_b]^T + bih (+bhh for r,z) ----
__global__ void __launch_bounds__(256) k_gi(const float* __restrict__ tt,
                                            const float* __restrict__ Wih_a,
                                            const float* __restrict__ Wih_b,
                                            const float* __restrict__ bih_a,
                                            const float* __restrict__ bih_b,
                                            const float* __restrict__ bhh_a,
                                            const float* __restrict__ bhh_b) {
    __shared__ float As[64][33];
    __shared__ float Bs[64][68];
    const int m0  = blockIdx.x * 32;
    const int n0  = blockIdx.y * 64;
    const int tid = threadIdx.x;
    const int tx  = tid & 15;
    const int ty  = tid >> 4;
    float acc[2][4];
#pragma unroll
    for (int a = 0; a < 2; a++)
#pragma unroll
        for (int b = 0; b < 4; b++) acc[a][b] = 0.f;

    for (int k0 = 0; k0 < 129; k0 += 64) {
        for (int l = tid; l < 64 * 32; l += 256) {
            int kk = l & 63, mm = l >> 6;
            int k = k0 + kk;
            float v = 0.f;
            if (k < 128)       v = g_emb[(m0 + mm) * E_ + k];
            else if (k == 128) v = tt[m0 + mm];
            As[kk][mm] = v;
        }
        for (int l = tid; l < 64 * 64; l += 256) {
            int kk = l & 63, e = l >> 6;
            int k = k0 + kk;
            int g = n0 + e;
            float v = 0.f;
            if (k < 129)
                v = (g < G3) ? Wih_a[g * 129 + k] : Wih_b[(g - G3) * 129 + k];
            Bs[kk][e] = v;
        }
        __syncthreads();
#pragma unroll 8
        for (int kk = 0; kk < 64; kk++) {
            float a0 = As[kk][ty * 2];
            float a1 = As[kk][ty * 2 + 1];
            float4 bv = *(const float4*)&Bs[kk][tx * 4];
            acc[0][0] += a0 * bv.x; acc[0][1] += a0 * bv.y;
            acc[0][2] += a0 * bv.z; acc[0][3] += a0 * bv.w;
            acc[1][0] += a1 * bv.x; acc[1][1] += a1 * bv.y;
            acc[1][2] += a1 * bv.z; acc[1][3] += a1 * bv.w;
        }
        __syncthreads();
    }
#pragma unroll
    for (int a = 0; a < 2; a++)
#pragma unroll
        for (int b = 0; b < 4; b++) {
            int g  = n0 + tx * 4 + b;
            int gg = (g < G3) ? g : g - G3;
            float bias = (g < G3) ? bih_a[gg] : bih_b[gg];
            if (gg < 256)                           // r,z gates: fold bhh too
                bias += (g < G3) ? bhh_a[gg] : bhh_b[gg];
            g_GI[(m0 + ty * 2 + a) * NG + g] = acc[a][b] + bias;
        }
}

// ---------------- K3: GRU recurrence, one GRU per CTA, weights fully in smem
// 148 CTAs (74 per GRU), 256 threads. Item = (query i, batch-group of 8).
// Serpentine longest-first schedule; GRU-a emits scores, GRU-b emits hb rows.
__global__ void __launch_bounds__(256, 1)
k_gru(const float* __restrict__ Whh_a, const float* __restrict__ Whh_b,
      const float* __restrict__ bhh_a, const float* __restrict__ bhh_b,
      const float* __restrict__ w_alpha, const float* __restrict__ b_alpha)
{
    extern __shared__ float ws[];       // [384][WPAD]
    __shared__ float sh_h[2][E_][8];    // [buf][hdim][row]
    __shared__ float sh_wal[E_];
    __shared__ float sh_bal;

    const int tid = threadIdx.x;
    const int gru = blockIdx.x & 1;
    const int c   = blockIdx.x >> 1;    // 0..73
    const int q   = tid >> 7;           // row-half: rows 4q..4q+3
    const int e   = tid & 127;

    const float* __restrict__ W = gru ? Whh_b : Whh_a;   // [384][128] row-major
    for (int l = tid; l < G3 * E_; l += 256)
        ws[(l >> 7) * WPAD + (l & 127)] = W[l];
    if (tid < E_) sh_wal[tid] = w_alpha[tid];
    if (tid == 0) sh_bal = b_alpha[0];
    const float bhhn = (gru ? bhh_b : bhh_a)[256 + e];

    const float* __restrict__ wr = ws + e * WPAD;
    const float* __restrict__ wz = ws + (e + 128) * WPAD;
    const float* __restrict__ wn = ws + (e + 256) * WPAD;

    // serpentine static schedule over 256 items (idx: i = 63-(idx>>2), bo = idx&3)
    int items[4]; int nit = 3;
    items[0] = c; items[1] = 147 - c; items[2] = 148 + c;
    if (c >= 40) { items[3] = 295 - c; nit = 4; }

    for (int it = 0; it < nit; it++) {
        const int idx = items[it];
        const int i   = 63 - (idx >> 2);
        const int bo  = idx & 3;

        for (int l = tid; l < E_ * 8; l += 256) ((float*)sh_h[1])[l] = 0.f;
        __syncthreads();   // also covers ws load on first item

        for (int k = 0; k <= i; k++) {
            const int j = i - k;
            const int cur = k & 1, prev = cur ^ 1;

            // GI loads — issued early, consumed only at gate combine
            float gir[4], giz[4], gin[4];
            {
                const float* gp = g_GI + ((bo * 8 + 4 * q) * T_ + j) * NG + gru * G3 + e;
#pragma unroll
                for (int rr = 0; rr < 4; rr++) {
                    gir[rr] = gp[0]; giz[rr] = gp[128]; gin[rr] = gp[256];
                    gp += T_ * NG;
                }
            }

            // gh GEMM: 4 rows x 3 gates, all operands in smem
            float aR[4] = {0.f,0.f,0.f,0.f};
            float aZ[4] = {0.f,0.f,0.f,0.f};
            float aN[4] = {0.f,0.f,0.f,0.f};
            const float* hp = &sh_h[prev][0][0] + 4 * q;
#pragma unroll 8
            for (int kq = 0; kq < 32; kq++) {
                const int kk = kq * 4;
                float4 r4 = *(const float4*)(wr + kk);
                float4 z4 = *(const float4*)(wz + kk);
                float4 n4 = *(const float4*)(wn + kk);
                float4 hh0 = *(const float4*)(hp + kk * 8);
                float4 hh1 = *(const float4*)(hp + kk * 8 + 8);
                float4 hh2 = *(const float4*)(hp + kk * 8 + 16);
                float4 hh3 = *(const float4*)(hp + kk * 8 + 24);
                float wrs[4] = {r4.x, r4.y, r4.z, r4.w};
                float wzs[4] = {z4.x, z4.y, z4.z, z4.w};
                float wns[4] = {n4.x, n4.y, n4.z, n4.w};
                float4 hv[4] = {hh0, hh1, hh2, hh3};
#pragma unroll
                for (int s = 0; s < 4; s++) {
                    const float* h = (const float*)&hv[s];
#pragma unroll
                    for (int rr = 0; rr < 4; rr++) {
                        aR[rr] += wrs[s] * h[rr];
                        aZ[rr] += wzs[s] * h[rr];
                        aN[rr] += wns[s] * h[rr];
                    }
                }
            }

            // gate combine in registers; write h_new into cur buffer
            {
                float4 hold = *(const float4*)(&sh_h[prev][e][4 * q]);
                const float* ho = (const float*)&hold;
                float hn[4];
#pragma unroll
                for (int rr = 0; rr < 4; rr++) {
                    float rg = fast_sigmoid(gir[rr] + aR[rr]);   // bhh_r folded in GI
                    float zg = fast_sigmoid(giz[rr] + aZ[rr]);   // bhh_z folded in GI
                    float ng = fast_tanh(gin[rr] + rg * (aN[rr] + bhhn));
                    hn[rr] = (1.f - zg) * ng + zg * ho[rr];
                }
                *(float4*)(&sh_h[cur][e][4 * q]) =
                    make_float4(hn[0], hn[1], hn[2], hn[3]);
                if (gru) {                                       // GRU-b: emit hb rows
#pragma unroll
                    for (int rr = 0; rr < 4; rr++) {
                        int b = bo * 8 + 4 * q + rr;
                        g_Hb[((b * T_ + i) * T_ + k) * E_ + e] = hn[rr];
                    }
                }
            }
            __syncthreads();

            // GRU-a: score s[b,i,k] = wal . ha + bal  (warp = row)
            if (!gru) {
                const int row = tid >> 5, lane = tid & 31;
                float p = sh_h[cur][lane][row]       * sh_wal[lane]
                        + sh_h[cur][lane + 32][row]  * sh_wal[lane + 32]
                        + sh_h[cur][lane + 64][row]  * sh_wal[lane + 64]
                        + sh_h[cur][lane + 96][row]  * sh_wal[lane + 96];
                p += __shfl_xor_sync(0xffffffffu, p, 16);
                p += __shfl_xor_sync(0xffffffffu, p, 8);
                p += __shfl_xor_sync(0xffffffffu, p, 4);
                p += __shfl_xor_sync(0xffffffffu, p, 2);
                p += __shfl_xor_sync(0xffffffffu, p, 1);
                if (lane == 0)
                    g_S[((bo * 8 + row) * T_ + i) * T_ + k] = p + sh_bal;
            }
        }
        __syncthreads();   // protect sh_h before next item's zeroing
    }
}

// ---------------- K4: beta GEMM + softmax attention + output ----------------
// Block = (b, i); 2048 blocks x 256 threads (8 k-rows x 32 lanes per tile).
__global__ void __launch_bounds__(256)
k_attn(const float* __restrict__ b_beta, const float* __restrict__ W_out,
       const float* __restrict__ b_out,  const int* __restrict__ lengths,
       float* __restrict__ out)
{
    __shared__ float hb_s[8][E_];
    __shared__ float u_s[T_];
    __shared__ float s_bbe[E_], s_wout[E_];

    const int blk = blockIdx.x;
    const int b   = blk >> 6;
    const int i   = blk & 63;
    const int tid = threadIdx.x;
    const int wr  = tid >> 5;       // k-row within tile
    const int lane = tid & 31;

    if (tid < E_) { s_bbe[tid] = b_beta[tid]; s_wout[tid] = W_out[tid]; }
    __syncthreads();

    for (int kt = 0; kt <= i; kt += 8) {
        for (int l = tid; l < 8 * E_; l += 256) {
            int r = l >> 7, e = l & 127;
            int k = kt + r;
            hb_s[r][e] = (k <= i) ? g_Hb[((b * T_ + i) * T_ + k) * E_ + e] : 0.f;
        }
        __syncthreads();
        const int k = kt + wr;
        if (k <= i) {
            const float* __restrict__ wb = g_Wbeta2 + (lane << 2);  // L1-resident
            const float* __restrict__ hr = hb_s[wr];
            float d0 = 0.f, d1 = 0.f, d2 = 0.f, d3 = 0.f;
#pragma unroll 8
            for (int kk = 0; kk < E_; kk++) {
                float hv = hr[kk];
                float4 wv = *(const float4*)(wb + kk * 128);
                d0 += hv * wv.x; d1 += hv * wv.y; d2 += hv * wv.z; d3 += hv * wv.w;
            }
            const int j = i - k;
            const float* ep = g_emb + (b * T_ + j) * E_ + lane;
            float u = fast_tanh(d0 + s_bbe[lane])      * ep[0]  * s_wout[lane]
                    + fast_tanh(d1 + s_bbe[lane + 32]) * ep[32] * s_wout[lane + 32]
                    + fast_tanh(d2 + s_bbe[lane + 64]) * ep[64] * s_wout[lane + 64]
                    + fast_tanh(d3 + s_bbe[lane + 96]) * ep[96] * s_wout[lane + 96];
            u += __shfl_xor_sync(0xffffffffu, u, 16);
            u += __shfl_xor_sync(0xffffffffu, u, 8);
            u += __shfl_xor_sync(0xffffffffu, u, 4);
            u += __shfl_xor_sync(0xffffffffu, u, 2);
            u += __shfl_xor_sync(0xffffffffu, u, 1);
            if (lane == 0) u_s[k] = u;
        }
        __syncthreads();
    }

    // softmax over k = 0..i and final output (warp 0)
    if (wr == 0) {
        const float* sp = g_S + (b * T_ + i) * T_;
        float s0 = (lane <= i)      ? sp[lane]      : -INFINITY;
        float s1 = (lane + 32 <= i) ? sp[lane + 32] : -INFINITY;
        float mx = fmaxf(s0, s1);
#pragma unroll
        for (int o = 16; o; o >>= 1)
            mx = fmaxf(mx, __shfl_xor_sync(0xffffffffu, mx, o));
        float e0 = (lane <= i)      ? __expf(s0 - mx) : 0.f;
        float e1 = (lane + 32 <= i) ? __expf(s1 - mx) : 0.f;
        float num = e0 * ((lane <= i)      ? u_s[lane]      : 0.f)
                  + e1 * ((lane + 32 <= i) ? u_s[lane + 32] : 0.f);
        float den = e0 + e1;
#pragma unroll
        for (int o = 16; o; o >>= 1) {
            num += __shfl_xor_sync(0xffffffffu, num, o);
            den += __shfl_xor_sync(0xffffffffu, den, o);
        }
        if (lane == 0) {
            float valid = (i < lengths[b]) ? 1.f : 0.f;
            out[b * T_ + i] = (num / den) * valid + b_out[0];
        }
    }
}

// ---------------- launch ----------------
extern "C" void kernel_launch(void* const* d_in, const int* in_sizes, int n_in,
                              void* d_out, int out_size) {
    const float* x       = (const float*)d_in[0];
    const float* tt      = (const float*)d_in[1];
    const int*   lengths = (const int*)  d_in[2];
    const float* Wemb    = (const float*)d_in[3];
    const float* Wih_a   = (const float*)d_in[4];
    const float* Whh_a   = (const float*)d_in[5];
    const float* bih_a   = (const float*)d_in[6];
    const float* bhh_a   = (const float*)d_in[7];
    const float* Wih_b   = (const float*)d_in[8];
    const float* Whh_b   = (const float*)d_in[9];
    const float* bih_b   = (const float*)d_in[10];
    const float* bhh_b   = (const float*)d_in[11];
    const float* w_alpha = (const float*)d_in[12];
    const float* b_alpha = (const float*)d_in[13];
    const float* W_beta  = (const float*)d_in[14];
    const float* b_beta  = (const float*)d_in[15];
    const float* W_out   = (const float*)d_in[16];
    const float* b_out   = (const float*)d_in[17];
    float* out = (float*)d_out;

    cudaFuncSetAttribute(k_gru, cudaFuncAttributeMaxDynamicSharedMemorySize,
                         GRU_SMEM);

    k_prep<<<64, 256>>>(W_beta);
    k_embed<<<128, 256>>>(x, Wemb);
    k_gi<<<dim3(64, 12), 256>>>(tt, Wih_a, Wih_b, bih_a, bih_b, bhh_a, bhh_b);
    k_gru<<<148, 256, GRU_SMEM>>>(Whh_a, Whh_b, bhh_a, bhh_b, w_alpha, b_alpha);
    k_attn<<<2048, 256>>>(b_beta, W_out, b_out, lengths, out);
}

// round 11
// speedup vs baseline: 1.7206x; 1.0211x over previous
#include <cuda_runtime.h>
#include <math.h>

#define B_   32
#define T_   64
#define BT   2048            // B*T
#define IND  4894
#define E_   128
#define G3   384             // 3*H
#define NG   768             // both GRUs' gates
#define WPAD 132             // smem stride for Whh rows (conflict-free float4)
#define GRU_SMEM  (G3 * WPAD * 4)    // 202752 B
#define ATTN_SMEM (E_ * E_ * 4)      // 65536 B (W_beta interleaved)

// ---------------- device scratch (no allocations allowed) ----------------
__device__ float g_emb[BT * E_];        // emb[m][e]  (atomicAdd target)
__device__ float g_GI [BT * NG];        // input gates + bih (+ bhh for r,z)
__device__ float g_Wbeta2[E_ * E_];     // [kk][(e&31)*4 + (e>>5)]
__device__ float g_Hb[BT * T_ * E_];    // hb states [b][i][k][e]
__device__ float g_S [BT * T_];         // scores [b][i][k]

__device__ __forceinline__ float fast_tanh(float x) {
    float y; asm("tanh.approx.f32 %0, %1;" : "=f"(y) : "f"(x)); return y;
}
__device__ __forceinline__ float fast_sigmoid(float x) {
    return 0.5f * fast_tanh(0.5f * x) + 0.5f;
}

// ---------------- K0: prep — W_beta interleave + zero g_emb ----------------
__global__ void k_prep(const float* __restrict__ W_beta) {
    int idx = blockIdx.x * 256 + threadIdx.x;
    if (idx < E_ * E_) {
        int kk = idx >> 7, e = idx & 127;
        g_Wbeta2[kk * 128 + ((e & 31) << 2) + (e >> 5)] = W_beta[e * E_ + kk];
    } else {
        int z = idx - E_ * E_;
        if (z < BT * E_) g_emb[z] = 0.f;
    }
}

// ---------------- K1: embedding GEMM  emb += x @ W_emb^T (split-K2) --------
// grid (64,2), 256 threads, BM=32 BN=128, 4m x 4n, register-prefetch DB.
__global__ void __launch_bounds__(256) k_embed(const float* __restrict__ x,
                                               const float* __restrict__ Wemb) {
    __shared__ float As[32][36];
    __shared__ float Bs[32][132];
    const int m0   = blockIdx.x * 32;
    const int kbeg = blockIdx.y * 2448;
    const int kend = (kbeg + 2448 < IND) ? (kbeg + 2448) : IND;
    const int tid  = threadIdx.x;
    const int tx   = tid & 31;
    const int ty   = tid >> 5;
    float acc[4][4];
#pragma unroll
    for (int a = 0; a < 4; a++)
#pragma unroll
        for (int b = 0; b < 4; b++) acc[a][b] = 0.f;

    float pa[4], pb[16];
    {   // prefetch first tile
#pragma unroll
        for (int u = 0; u < 4; u++) {
            int l = tid + 256 * u, kk = l & 31, mm = l >> 5, k = kbeg + kk;
            pa[u] = (k < kend) ? x[(m0 + mm) * IND + k] : 0.f;
        }
#pragma unroll
        for (int u = 0; u < 16; u++) {
            int l = tid + 256 * u, kk = l & 31, ee = l >> 5, k = kbeg + kk;
            pb[u] = (k < kend) ? Wemb[ee * IND + k] : 0.f;
        }
    }
    for (int k0 = kbeg; k0 < kend; k0 += 32) {
        __syncthreads();
#pragma unroll
        for (int u = 0; u < 4; u++) {
            int l = tid + 256 * u;
            As[l & 31][l >> 5] = pa[u];
        }
#pragma unroll
        for (int u = 0; u < 16; u++) {
            int l = tid + 256 * u;
            Bs[l & 31][l >> 5] = pb[u];
        }
        __syncthreads();
        int kn = k0 + 32;
        if (kn < kend) {
#pragma unroll
            for (int u = 0; u < 4; u++) {
                int l = tid + 256 * u, kk = l & 31, mm = l >> 5, k = kn + kk;
                pa[u] = (k < kend) ? x[(m0 + mm) * IND + k] : 0.f;
            }
#pragma unroll
            for (int u = 0; u < 16; u++) {
                int l = tid + 256 * u, kk = l & 31, ee = l >> 5, k = kn + kk;
                pb[u] = (k < kend) ? Wemb[ee * IND + k] : 0.f;
            }
        }
#pragma unroll
        for (int kk = 0; kk < 32; kk++) {
            float4 av = *(const float4*)&As[kk][ty * 4];
            float4 bv = *(const float4*)&Bs[kk][tx * 4];
            float am[4] = {av.x, av.y, av.z, av.w};
            float bn[4] = {bv.x, bv.y, bv.z, bv.w};
#pragma unroll
            for (int a = 0; a < 4; a++)
#pragma unroll
                for (int b = 0; b < 4; b++) acc[a][b] += am[a] * bn[b];
        }
    }
#pragma unroll
    for (int a = 0; a < 4; a++)
#pragma unroll
        for (int b = 0; b < 4; b++)
            atomicAdd(&g_emb[(m0 + ty * 4 + a) * E_ + tx * 4 + b], acc[a][b]);
}

// ---------------- K2: GI = temb @ [Wih_a | Wih_b]^T + bih (+bhh for r,z) ----
__global__ void __launch_bounds__(256) k_gi(const float* __restrict__ tt,
                                            const float* __restrict__ Wih_a,
                                            const float* __restrict__ Wih_b,
                                            const float* __restrict__ bih_a,
                                            const float* __restrict__ bih_b,
                                            const float* __restrict__ bhh_a,
                                            const float* __restrict__ bhh_b) {
    __shared__ float As[64][33];
    __shared__ float Bs[64][68];
    const int m0  = blockIdx.x * 32;
    const int n0  = blockIdx.y * 64;
    const int tid = threadIdx.x;
    const int tx  = tid & 15;
    const int ty  = tid >> 4;
    float acc[2][4];
#pragma unroll
    for (int a = 0; a < 2; a++)
#pragma unroll
        for (int b = 0; b < 4; b++) acc[a][b] = 0.f;

    for (int k0 = 0; k0 < 129; k0 += 64) {
        for (int l = tid; l < 64 * 32; l += 256) {
            int kk = l & 63, mm = l >> 6;
            int k = k0 + kk;
            float v = 0.f;
            if (k < 128)       v = g_emb[(m0 + mm) * E_ + k];
            else if (k == 128) v = tt[m0 + mm];
            As[kk][mm] = v;
        }
        for (int l = tid; l < 64 * 64; l += 256) {
            int kk = l & 63, e = l >> 6;
            int k = k0 + kk;
            int g = n0 + e;
            float v = 0.f;
            if (k < 129)
                v = (g < G3) ? Wih_a[g * 129 + k] : Wih_b[(g - G3) * 129 + k];
            Bs[kk][e] = v;
        }
        __syncthreads();
#pragma unroll 8
        for (int kk = 0; kk < 64; kk++) {
            float a0 = As[kk][ty * 2];
            float a1 = As[kk][ty * 2 + 1];
            float4 bv = *(const float4*)&Bs[kk][tx * 4];
            acc[0][0] += a0 * bv.x; acc[0][1] += a0 * bv.y;
            acc[0][2] += a0 * bv.z; acc[0][3] += a0 * bv.w;
            acc[1][0] += a1 * bv.x; acc[1][1] += a1 * bv.y;
            acc[1][2] += a1 * bv.z; acc[1][3] += a1 * bv.w;
        }
        __syncthreads();
    }
#pragma unroll
    for (int a = 0; a < 2; a++)
#pragma unroll
        for (int b = 0; b < 4; b++) {
            int g  = n0 + tx * 4 + b;
            int gg = (g < G3) ? g : g - G3;
            float bias = (g < G3) ? bih_a[gg] : bih_b[gg];
            if (gg < 256)
                bias += (g < G3) ? bhh_a[gg] : bhh_b[gg];
            g_GI[(m0 + ty * 2 + a) * NG + g] = acc[a][b] + bias;
        }
}

// ---------------- K3: GRU recurrence, one GRU/CTA, 16 batch rows per step ---
// 128 CTAs (64 per GRU). Item = (query i, batch-half of 16). CTA c runs items
// {c, 127-c} -> exactly 65 steps per CTA. Weights fully in smem.
__global__ void __launch_bounds__(256, 1)
k_gru(const float* __restrict__ Whh_a, const float* __restrict__ Whh_b,
      const float* __restrict__ bhh_a, const float* __restrict__ bhh_b,
      const float* __restrict__ w_alpha, const float* __restrict__ b_alpha)
{
    extern __shared__ float ws[];       // [384][WPAD]
    __shared__ float sh_h[2][E_][20];   // [buf][hdim][row16 + pad4]
    __shared__ float sh_wal[E_];
    __shared__ float sh_bal;

    const int tid = threadIdx.x;
    const int gru = blockIdx.x & 1;
    const int c   = blockIdx.x >> 1;    // 0..63
    const int q   = tid >> 7;           // 0/1 -> rows 8q..8q+7
    const int e   = tid & 127;

    const float* __restrict__ W = gru ? Whh_b : Whh_a;   // [384][128]
    for (int l = tid; l < G3 * E_; l += 256)
        ws[(l >> 7) * WPAD + (l & 127)] = W[l];
    if (tid < E_) sh_wal[tid] = w_alpha[tid];
    if (tid == 0) sh_bal = b_alpha[0];
    const float bhhn = (gru ? bhh_b : bhh_a)[256 + e];

    const float* __restrict__ wr = ws + e * WPAD;
    const float* __restrict__ wz = ws + (e + 128) * WPAD;
    const float* __restrict__ wn = ws + (e + 256) * WPAD;

    for (int it = 0; it < 2; it++) {
        const int idx  = it ? (127 - c) : c;
        const int i    = 63 - (idx >> 1);
        const int half = idx & 1;
        const int b0   = half * 16;     // batches b0..b0+15

        for (int l = tid; l < E_ * 20; l += 256) (&sh_h[1][0][0])[l] = 0.f;
        __syncthreads();

        for (int k = 0; k <= i; k++) {
            const int j = i - k;
            const int cur = k & 1, prev = cur ^ 1;

            // GI loads (independent of h; hidden under GEMM)
            float gir[8], giz[8], gin[8];
            {
                const float* gp = g_GI + ((b0 + 8 * q) * T_ + j) * NG + gru * G3 + e;
#pragma unroll
                for (int rr = 0; rr < 8; rr++) {
                    gir[rr] = gp[0]; giz[rr] = gp[128]; gin[rr] = gp[256];
                    gp += T_ * NG;
                }
            }

            // gh GEMM: 8 rows x 3 gates, all smem
            float aR[8] = {0,0,0,0,0,0,0,0};
            float aZ[8] = {0,0,0,0,0,0,0,0};
            float aN[8] = {0,0,0,0,0,0,0,0};
            const float* hb_ = &sh_h[prev][0][0] + 8 * q;
#pragma unroll 4
            for (int kq = 0; kq < 32; kq++) {
                const int kk = kq * 4;
                float4 r4 = *(const float4*)(wr + kk);
                float4 z4 = *(const float4*)(wz + kk);
                float4 n4 = *(const float4*)(wn + kk);
                const float wrs[4] = {r4.x, r4.y, r4.z, r4.w};
                const float wzs[4] = {z4.x, z4.y, z4.z, z4.w};
                const float wns[4] = {n4.x, n4.y, n4.z, n4.w};
#pragma unroll
                for (int s = 0; s < 4; s++) {
                    float4 h0 = *(const float4*)(hb_ + (kk + s) * 20);
                    float4 h1 = *(const float4*)(hb_ + (kk + s) * 20 + 4);
                    float hh[8] = {h0.x, h0.y, h0.z, h0.w, h1.x, h1.y, h1.z, h1.w};
#pragma unroll
                    for (int rr = 0; rr < 8; rr++) {
                        aR[rr] += wrs[s] * hh[rr];
                        aZ[rr] += wzs[s] * hh[rr];
                        aN[rr] += wns[s] * hh[rr];
                    }
                }
            }

            // gate combine; write h_new; GRU-b emits hb rows
            {
                float4 ho0 = *(const float4*)(&sh_h[prev][e][8 * q]);
                float4 ho1 = *(const float4*)(&sh_h[prev][e][8 * q + 4]);
                float ho[8] = {ho0.x, ho0.y, ho0.z, ho0.w, ho1.x, ho1.y, ho1.z, ho1.w};
                float hn[8];
#pragma unroll
                for (int rr = 0; rr < 8; rr++) {
                    float rg = fast_sigmoid(gir[rr] + aR[rr]);   // bhh_r in GI
                    float zg = fast_sigmoid(giz[rr] + aZ[rr]);   // bhh_z in GI
                    float ng = fast_tanh(gin[rr] + rg * (aN[rr] + bhhn));
                    hn[rr] = (1.f - zg) * ng + zg * ho[rr];
                }
                *(float4*)(&sh_h[cur][e][8 * q])     = make_float4(hn[0], hn[1], hn[2], hn[3]);
                *(float4*)(&sh_h[cur][e][8 * q + 4]) = make_float4(hn[4], hn[5], hn[6], hn[7]);
                if (gru) {
#pragma unroll
                    for (int rr = 0; rr < 8; rr++) {
                        int b = b0 + 8 * q + rr;
                        g_Hb[((b * T_ + i) * T_ + k) * E_ + e] = hn[rr];
                    }
                }
            }
            __syncthreads();

            // GRU-a: scores for rows 2w, 2w+1 (warp w)
            if (!gru) {
                const int w = tid >> 5, lane = tid & 31;
                const int r0 = 2 * w, r1 = 2 * w + 1;
                float p0 = 0.f, p1 = 0.f;
#pragma unroll
                for (int qq = 0; qq < 4; qq++) {
                    int ee = lane + 32 * qq;
                    float wv = sh_wal[ee];
                    p0 += sh_h[cur][ee][r0] * wv;
                    p1 += sh_h[cur][ee][r1] * wv;
                }
#pragma unroll
                for (int o = 16; o; o >>= 1) {
                    p0 += __shfl_xor_sync(0xffffffffu, p0, o);
                    p1 += __shfl_xor_sync(0xffffffffu, p1, o);
                }
                if (lane == 0) {
                    g_S[((b0 + r0) * T_ + i) * T_ + k] = p0 + sh_bal;
                    g_S[((b0 + r1) * T_ + i) * T_ + k] = p1 + sh_bal;
                }
            }
        }
        __syncthreads();    // protect sh_h before next item's zeroing
    }
}

// ---------------- K4: beta GEMM + softmax + output --------------------------
// Block = (b, i-quad {iq, 63-iq, 16+iq, 47-iq}); 512 balanced blocks.
// W_beta cached in smem (conflict-free LDS.128).
__global__ void __launch_bounds__(256)
k_attn(const float* __restrict__ b_beta, const float* __restrict__ W_out,
       const float* __restrict__ b_out,  const int* __restrict__ lengths,
       float* __restrict__ out)
{
    extern __shared__ float wsb[];      // [kk][lane*4+q]  16384 floats
    __shared__ float hb_s[8][E_];
    __shared__ float u_s[T_];
    __shared__ float s_bbe[E_], s_wout[E_];

    const int blk = blockIdx.x;
    const int b   = blk >> 4;
    const int iq  = blk & 15;
    const int tid = threadIdx.x;
    const int wr  = tid >> 5;
    const int lane = tid & 31;

    for (int l = tid; l < E_ * E_ / 4; l += 256)
        ((float4*)wsb)[l] = ((const float4*)g_Wbeta2)[l];
    if (tid < E_) { s_bbe[tid] = b_beta[tid]; s_wout[tid] = W_out[tid]; }
    __syncthreads();

    const int ilist[4] = {iq, 63 - iq, 16 + iq, 47 - iq};

    for (int iv = 0; iv < 4; iv++) {
        const int i = ilist[iv];

        for (int kt = 0; kt <= i; kt += 8) {
            for (int l = tid; l < 8 * E_; l += 256) {
                int r = l >> 7, e = l & 127;
                int k = kt + r;
                hb_s[r][e] = (k <= i) ? g_Hb[((b * T_ + i) * T_ + k) * E_ + e] : 0.f;
            }
            __syncthreads();
            const int k = kt + wr;
            if (k <= i) {
                const float* __restrict__ wb = wsb + (lane << 2);
                const float* __restrict__ hr = hb_s[wr];
                float d0 = 0.f, d1 = 0.f, d2 = 0.f, d3 = 0.f;
#pragma unroll 8
                for (int kk = 0; kk < E_; kk++) {
                    float hv = hr[kk];
                    float4 wv = *(const float4*)(wb + kk * 128);
                    d0 += hv * wv.x; d1 += hv * wv.y; d2 += hv * wv.z; d3 += hv * wv.w;
                }
                const int j = i - k;
                const float* ep = g_emb + (b * T_ + j) * E_ + lane;
                float u = fast_tanh(d0 + s_bbe[lane])      * ep[0]  * s_wout[lane]
                        + fast_tanh(d1 + s_bbe[lane + 32]) * ep[32] * s_wout[lane + 32]
                        + fast_tanh(d2 + s_bbe[lane + 64]) * ep[64] * s_wout[lane + 64]
                        + fast_tanh(d3 + s_bbe[lane + 96]) * ep[96] * s_wout[lane + 96];
#pragma unroll
                for (int o = 16; o; o >>= 1)
                    u += __shfl_xor_sync(0xffffffffu, u, o);
                if (lane == 0) u_s[k] = u;
            }
            __syncthreads();
        }

        if (wr == 0) {   // softmax over k = 0..i and output
            const float* sp = g_S + (b * T_ + i) * T_;
            float s0 = (lane <= i)      ? sp[lane]      : -INFINITY;
            float s1 = (lane + 32 <= i) ? sp[lane + 32] : -INFINITY;
            float mx = fmaxf(s0, s1);
#pragma unroll
            for (int o = 16; o; o >>= 1)
                mx = fmaxf(mx, __shfl_xor_sync(0xffffffffu, mx, o));
            float e0 = (lane <= i)      ? __expf(s0 - mx) : 0.f;
            float e1 = (lane + 32 <= i) ? __expf(s1 - mx) : 0.f;
            float num = e0 * ((lane <= i)      ? u_s[lane]      : 0.f)
                      + e1 * ((lane + 32 <= i) ? u_s[lane + 32] : 0.f);
            float den = e0 + e1;
#pragma unroll
            for (int o = 16; o; o >>= 1) {
                num += __shfl_xor_sync(0xffffffffu, num, o);
                den += __shfl_xor_sync(0xffffffffu, den, o);
            }
            if (lane == 0) {
                float valid = (i < lengths[b]) ? 1.f : 0.f;
                out[b * T_ + i] = (num / den) * valid + b_out[0];
            }
        }
        __syncthreads();
    }
}

// ---------------- launch ----------------
extern "C" void kernel_launch(void* const* d_in, const int* in_sizes, int n_in,
                              void* d_out, int out_size) {
    const float* x       = (const float*)d_in[0];
    const float* tt      = (const float*)d_in[1];
    const int*   lengths = (const int*)  d_in[2];
    const float* Wemb    = (const float*)d_in[3];
    const float* Wih_a   = (const float*)d_in[4];
    const float* Whh_a   = (const float*)d_in[5];
    const float* bih_a   = (const float*)d_in[6];
    const float* bhh_a   = (const float*)d_in[7];
    const float* Wih_b   = (const float*)d_in[8];
    const float* Whh_b   = (const float*)d_in[9];
    const float* bih_b   = (const float*)d_in[10];
    const float* bhh_b   = (const float*)d_in[11];
    const float* w_alpha = (const float*)d_in[12];
    const float* b_alpha = (const float*)d_in[13];
    const float* W_beta  = (const float*)d_in[14];
    const float* b_beta  = (const float*)d_in[15];
    const float* W_out   = (const float*)d_in[16];
    const float* b_out   = (const float*)d_in[17];
    float* out = (float*)d_out;

    cudaFuncSetAttribute(k_gru, cudaFuncAttributeMaxDynamicSharedMemorySize,
                         GRU_SMEM);
    cudaFuncSetAttribute(k_attn, cudaFuncAttributeMaxDynamicSharedMemorySize,
                         ATTN_SMEM);

    k_prep<<<1088, 256>>>(W_beta);
    k_embed<<<dim3(64, 2), 256>>>(x, Wemb);
    k_gi<<<dim3(64, 12), 256>>>(tt, Wih_a, Wih_b, bih_a, bih_b, bhh_a, bhh_b);
    k_gru<<<128, 256, GRU_SMEM>>>(Whh_a, Whh_b, bhh_a, bhh_b, w_alpha, b_alpha);
    k_attn<<<512, 256, ATTN_SMEM>>>(b_beta, W_out, b_out, lengths, out);
}

// round 13
// speedup vs baseline: 2.1765x; 1.2649x over previous
#include <cuda_runtime.h>
#include <math.h>

#define B_   32
#define T_   64
#define BT   2048            // B*T
#define IND  4894
#define E_   128
#define G3   384             // 3*H
#define NG   768             // both GRUs' gates
#define WPAD 132             // smem stride for Whh rows (conflict-free float4)
#define GRU_SMEM  (G3 * WPAD * 4)    // 202752 B
#define ATTN_SMEM (E_ * E_ * 4)      // 65536 B (W_beta interleaved)

typedef unsigned long long u64;

// ---------------- device scratch (no allocations allowed) ----------------
__device__ float g_emb[BT * E_];        // emb[m][e]  (atomicAdd target)
__device__ float g_GI [BT * NG];        // input gates + bih (+ bhh for r,z)
__device__ float g_Wbeta2[E_ * E_];     // [kk][(e&31)*4 + (e>>5)]
__device__ float g_Hb[BT * T_ * E_];    // hb states [b][i][k][e]
__device__ float g_S [BT * T_];         // scores [b][i][k]

__device__ __forceinline__ float fast_tanh(float x) {
    float y; asm("tanh.approx.f32 %0, %1;" : "=f"(y) : "f"(x)); return y;
}
__device__ __forceinline__ float fast_sigmoid(float x) {
    return 0.5f * fast_tanh(0.5f * x) + 0.5f;
}
// packed fp32x2 helpers (Blackwell)
__device__ __forceinline__ u64 pack2(float x) {
    u64 r; asm("mov.b64 %0, {%1, %1};" : "=l"(r) : "f"(x)); return r;
}
__device__ __forceinline__ void fma2(u64 &acc, u64 w, u64 h) {
    asm("fma.rn.f32x2 %0, %1, %2, %3;" : "=l"(acc) : "l"(w), "l"(h), "l"(acc));
}
__device__ __forceinline__ float2 unpack2(u64 v) {
    float2 f; asm("mov.b64 {%0, %1}, %2;" : "=f"(f.x), "=f"(f.y) : "l"(v)); return f;
}

// ---------------- K0: prep — W_beta interleave + zero g_emb ----------------
__global__ void k_prep(const float* __restrict__ W_beta) {
    int idx = blockIdx.x * 256 + threadIdx.x;
    if (idx < E_ * E_) {
        int kk = idx >> 7, e = idx & 127;
        g_Wbeta2[kk * 128 + ((e & 31) << 2) + (e >> 5)] = W_beta[e * E_ + kk];
    } else {
        int z = idx - E_ * E_;
        if (z < BT * E_) g_emb[z] = 0.f;
    }
}

// ---------------- K1: embedding GEMM  emb += x @ W_emb^T (split-K2) --------
__global__ void __launch_bounds__(256) k_embed(const float* __restrict__ x,
                                               const float* __restrict__ Wemb) {
    __shared__ float As[32][36];
    __shared__ float Bs[32][132];
    const int m0   = blockIdx.x * 32;
    const int kbeg = blockIdx.y * 2448;
    const int kend = (kbeg + 2448 < IND) ? (kbeg + 2448) : IND;
    const int tid  = threadIdx.x;
    const int tx   = tid & 31;
    const int ty   = tid >> 5;
    float acc[4][4];
#pragma unroll
    for (int a = 0; a < 4; a++)
#pragma unroll
        for (int b = 0; b < 4; b++) acc[a][b] = 0.f;

    float pa[4], pb[16];
    {
#pragma unroll
        for (int u = 0; u < 4; u++) {
            int l = tid + 256 * u, kk = l & 31, mm = l >> 5, k = kbeg + kk;
            pa[u] = (k < kend) ? x[(m0 + mm) * IND + k] : 0.f;
        }
#pragma unroll
        for (int u = 0; u < 16; u++) {
            int l = tid + 256 * u, kk = l & 31, ee = l >> 5, k = kbeg + kk;
            pb[u] = (k < kend) ? Wemb[ee * IND + k] : 0.f;
        }
    }
    for (int k0 = kbeg; k0 < kend; k0 += 32) {
        __syncthreads();
#pragma unroll
        for (int u = 0; u < 4; u++) {
            int l = tid + 256 * u;
            As[l & 31][l >> 5] = pa[u];
        }
#pragma unroll
        for (int u = 0; u < 16; u++) {
            int l = tid + 256 * u;
            Bs[l & 31][l >> 5] = pb[u];
        }
        __syncthreads();
        int kn = k0 + 32;
        if (kn < kend) {
#pragma unroll
            for (int u = 0; u < 4; u++) {
                int l = tid + 256 * u, kk = l & 31, mm = l >> 5, k = kn + kk;
                pa[u] = (k < kend) ? x[(m0 + mm) * IND + k] : 0.f;
            }
#pragma unroll
            for (int u = 0; u < 16; u++) {
                int l = tid + 256 * u, kk = l & 31, ee = l >> 5, k = kn + kk;
                pb[u] = (k < kend) ? Wemb[ee * IND + k] : 0.f;
            }
        }
#pragma unroll
        for (int kk = 0; kk < 32; kk++) {
            float4 av = *(const float4*)&As[kk][ty * 4];
            float4 bv = *(const float4*)&Bs[kk][tx * 4];
            float am[4] = {av.x, av.y, av.z, av.w};
            float bn[4] = {bv.x, bv.y, bv.z, bv.w};
#pragma unroll
            for (int a = 0; a < 4; a++)
#pragma unroll
                for (int b = 0; b < 4; b++) acc[a][b] += am[a] * bn[b];
        }
    }
#pragma unroll
    for (int a = 0; a < 4; a++)
#pragma unroll
        for (int b = 0; b < 4; b++)
            atomicAdd(&g_emb[(m0 + ty * 4 + a) * E_ + tx * 4 + b], acc[a][b]);
}

// ---------------- K2: GI = temb @ [Wih_a | Wih_b]^T + bih (+bhh for r,z) ----
__global__ void __launch_bounds__(256) k_gi(const float* __restrict__ tt,
                                            const float* __restrict__ Wih_a,
                                            const float* __restrict__ Wih_b,
                                            const float* __restrict__ bih_a,
                                            const float* __restrict__ bih_b,
                                            const float* __restrict__ bhh_a,
                                            const float* __restrict__ bhh_b) {
    __shared__ float As[64][33];
    __shared__ float Bs[64][68];
    const int m0  = blockIdx.x * 32;
    const int n0  = blockIdx.y * 64;
    const int tid = threadIdx.x;
    const int tx  = tid & 15;
    const int ty  = tid >> 4;
    float acc[2][4];
#pragma unroll
    for (int a = 0; a < 2; a++)
#pragma unroll
        for (int b = 0; b < 4; b++) acc[a][b] = 0.f;

    for (int k0 = 0; k0 < 129; k0 += 64) {
        for (int l = tid; l < 64 * 32; l += 256) {
            int kk = l & 63, mm = l >> 6;
            int k = k0 + kk;
            float v = 0.f;
            if (k < 128)       v = g_emb[(m0 + mm) * E_ + k];
            else if (k == 128) v = tt[m0 + mm];
            As[kk][mm] = v;
        }
        for (int l = tid; l < 64 * 64; l += 256) {
            int kk = l & 63, e = l >> 6;
            int k = k0 + kk;
            int g = n0 + e;
            float v = 0.f;
            if (k < 129)
                v = (g < G3) ? Wih_a[g * 129 + k] : Wih_b[(g - G3) * 129 + k];
            Bs[kk][e] = v;
        }
        __syncthreads();
#pragma unroll 8
        for (int kk = 0; kk < 64; kk++) {
            float a0 = As[kk][ty * 2];
            float a1 = As[kk][ty * 2 + 1];
            float4 bv = *(const float4*)&Bs[kk][tx * 4];
            acc[0][0] += a0 * bv.x; acc[0][1] += a0 * bv.y;
            acc[0][2] += a0 * bv.z; acc[0][3] += a0 * bv.w;
            acc[1][0] += a1 * bv.x; acc[1][1] += a1 * bv.y;
            acc[1][2] += a1 * bv.z; acc[1][3] += a1 * bv.w;
        }
        __syncthreads();
    }
#pragma unroll
    for (int a = 0; a < 2; a++)
#pragma unroll
        for (int b = 0; b < 4; b++) {
            int g  = n0 + tx * 4 + b;
            int gg = (g < G3) ? g : g - G3;
            float bias = (g < G3) ? bih_a[gg] : bih_b[gg];
            if (gg < 256)
                bias += (g < G3) ? bhh_a[gg] : bhh_b[gg];
            g_GI[(m0 + ty * 2 + a) * NG + g] = acc[a][b] + bias;
        }
}

// ---------------- K3: GRU recurrence with packed f32x2 FMA ------------------
// 128 CTAs (64 per GRU). Item = (query i, batch-half of 16). CTA c runs items
// {c, 127-c} -> exactly 65 steps per CTA. Whh fully in smem.
__global__ void __launch_bounds__(256, 1)
k_gru(const float* __restrict__ Whh_a, const float* __restrict__ Whh_b,
      const float* __restrict__ bhh_a, const float* __restrict__ bhh_b,
      const float* __restrict__ w_alpha, const float* __restrict__ b_alpha)
{
    extern __shared__ float ws[];       // [384][WPAD]
    __shared__ float sh_h[2][E_][20];   // [buf][hdim][row16 + pad4]
    __shared__ float sh_wal[E_];
    __shared__ float sh_bal;

    const int tid = threadIdx.x;
    const int gru = blockIdx.x & 1;
    const int c   = blockIdx.x >> 1;    // 0..63
    const int q   = tid >> 7;           // 0/1 -> rows 8q..8q+7
    const int e   = tid & 127;

    const float* __restrict__ W = gru ? Whh_b : Whh_a;   // [384][128]
    for (int l = tid; l < G3 * E_; l += 256)
        ws[(l >> 7) * WPAD + (l & 127)] = W[l];
    if (tid < E_) sh_wal[tid] = w_alpha[tid];
    if (tid == 0) sh_bal = b_alpha[0];
    const float bhhn = (gru ? bhh_b : bhh_a)[256 + e];

    const float* __restrict__ wrp = ws + e * WPAD;
    const float* __restrict__ wzp = ws + (e + 128) * WPAD;
    const float* __restrict__ wnp = ws + (e + 256) * WPAD;

    for (int it = 0; it < 2; it++) {
        const int idx  = it ? (127 - c) : c;
        const int i    = 63 - (idx >> 1);
        const int half = idx & 1;
        const int b0   = half * 16;     // batches b0..b0+15

        for (int l = tid; l < E_ * 20; l += 256) (&sh_h[1][0][0])[l] = 0.f;
        __syncthreads();

        for (int k = 0; k <= i; k++) {
            const int j = i - k;
            const int cur = k & 1, prev = cur ^ 1;

            // GI loads (independent of h; hidden under GEMM)
            float gir[8], giz[8], gin[8];
            {
                const float* gp = g_GI + ((b0 + 8 * q) * T_ + j) * NG + gru * G3 + e;
#pragma unroll
                for (int rr = 0; rr < 8; rr++) {
                    gir[rr] = gp[0]; giz[rr] = gp[128]; gin[rr] = gp[256];
                    gp += T_ * NG;
                }
            }

            // gh GEMM: 8 rows x 3 gates, packed f32x2 (row pairs)
            u64 aR2[4], aZ2[4], aN2[4];
#pragma unroll
            for (int p = 0; p < 4; p++) { aR2[p] = 0ULL; aZ2[p] = 0ULL; aN2[p] = 0ULL; }
            const float* hb_ = &sh_h[prev][0][0] + 8 * q;
#pragma unroll 4
            for (int kq = 0; kq < 32; kq++) {
                const int kk = kq * 4;
                float4 r4 = *(const float4*)(wrp + kk);
                float4 z4 = *(const float4*)(wzp + kk);
                float4 n4 = *(const float4*)(wnp + kk);
                const float wrs[4] = {r4.x, r4.y, r4.z, r4.w};
                const float wzs[4] = {z4.x, z4.y, z4.z, z4.w};
                const float wns[4] = {n4.x, n4.y, n4.z, n4.w};
#pragma unroll
                for (int s = 0; s < 4; s++) {
                    ulonglong2 hA = *(const ulonglong2*)(hb_ + (kk + s) * 20);
                    ulonglong2 hB = *(const ulonglong2*)(hb_ + (kk + s) * 20 + 4);
                    u64 w2;
                    w2 = pack2(wrs[s]);
                    fma2(aR2[0], w2, hA.x); fma2(aR2[1], w2, hA.y);
                    fma2(aR2[2], w2, hB.x); fma2(aR2[3], w2, hB.y);
                    w2 = pack2(wzs[s]);
                    fma2(aZ2[0], w2, hA.x); fma2(aZ2[1], w2, hA.y);
                    fma2(aZ2[2], w2, hB.x); fma2(aZ2[3], w2, hB.y);
                    w2 = pack2(wns[s]);
                    fma2(aN2[0], w2, hA.x); fma2(aN2[1], w2, hA.y);
                    fma2(aN2[2], w2, hB.x); fma2(aN2[3], w2, hB.y);
                }
            }
            // unpack accumulators
            float aR[8], aZ[8], aN[8];
#pragma unroll
            for (int p = 0; p < 4; p++) {
                float2 v;
                v = unpack2(aR2[p]); aR[2*p] = v.x; aR[2*p+1] = v.y;
                v = unpack2(aZ2[p]); aZ[2*p] = v.x; aZ[2*p+1] = v.y;
                v = unpack2(aN2[p]); aN[2*p] = v.x; aN[2*p+1] = v.y;
            }

            // gate combine; write h_new; GRU-b emits hb rows
            {
                float4 ho0 = *(const float4*)(&sh_h[prev][e][8 * q]);
                float4 ho1 = *(const float4*)(&sh_h[prev][e][8 * q + 4]);
                float ho[8] = {ho0.x, ho0.y, ho0.z, ho0.w, ho1.x, ho1.y, ho1.z, ho1.w};
                float hn[8];
#pragma unroll
                for (int rr = 0; rr < 8; rr++) {
                    float rg = fast_sigmoid(gir[rr] + aR[rr]);   // bhh_r in GI
                    float zg = fast_sigmoid(giz[rr] + aZ[rr]);   // bhh_z in GI
                    float ng = fast_tanh(gin[rr] + rg * (aN[rr] + bhhn));
                    hn[rr] = (1.f - zg) * ng + zg * ho[rr];
                }
                *(float4*)(&sh_h[cur][e][8 * q])     = make_float4(hn[0], hn[1], hn[2], hn[3]);
                *(float4*)(&sh_h[cur][e][8 * q + 4]) = make_float4(hn[4], hn[5], hn[6], hn[7]);
                if (gru) {
#pragma unroll
                    for (int rr = 0; rr < 8; rr++) {
                        int b = b0 + 8 * q + rr;
                        g_Hb[((b * T_ + i) * T_ + k) * E_ + e] = hn[rr];
                    }
                }
            }
            __syncthreads();

            // GRU-a: scores for rows 2w, 2w+1 (warp w)
            if (!gru) {
                const int w = tid >> 5, lane = tid & 31;
                const int r0 = 2 * w, r1 = 2 * w + 1;
                float p0 = 0.f, p1 = 0.f;
#pragma unroll
                for (int qq = 0; qq < 4; qq++) {
                    int ee = lane + 32 * qq;
                    float wv = sh_wal[ee];
                    p0 += sh_h[cur][ee][r0] * wv;
                    p1 += sh_h[cur][ee][r1] * wv;
                }
#pragma unroll
                for (int o = 16; o; o >>= 1) {
                    p0 += __shfl_xor_sync(0xffffffffu, p0, o);
                    p1 += __shfl_xor_sync(0xffffffffu, p1, o);
                }
                if (lane == 0) {
                    g_S[((b0 + r0) * T_ + i) * T_ + k] = p0 + sh_bal;
                    g_S[((b0 + r1) * T_ + i) * T_ + k] = p1 + sh_bal;
                }
            }
        }
        __syncthreads();    // protect sh_h before next item's zeroing
    }
}

// ---------------- K4: beta GEMM + softmax + output --------------------------
// Block = (b, i-quad); 512 blocks. 4 k-rows per warp (4x Wbeta LDS reuse).
__global__ void __launch_bounds__(256)
k_attn(const float* __restrict__ b_beta, const float* __restrict__ W_out,
       const float* __restrict__ b_out,  const int* __restrict__ lengths,
       float* __restrict__ out)
{
    extern __shared__ float wsb[];      // [kk][lane*4+q]  16384 floats
    __shared__ float hb_s[32][E_];      // 32 k-rows
    __shared__ float u_s[T_];
    __shared__ float s_bbe[E_], s_wout[E_];

    const int blk  = blockIdx.x;
    const int b    = blk >> 4;
    const int iq   = blk & 15;
    const int tid  = threadIdx.x;
    const int wrp  = tid >> 5;          // warp 0..7
    const int lane = tid & 31;

    for (int l = tid; l < E_ * E_ / 4; l += 256)
        ((float4*)wsb)[l] = ((const float4*)g_Wbeta2)[l];
    if (tid < E_) { s_bbe[tid] = b_beta[tid]; s_wout[tid] = W_out[tid]; }
    __syncthreads();

    const int ilist[4] = {iq, 63 - iq, 16 + iq, 47 - iq};

    for (int iv = 0; iv < 4; iv++) {
        const int i = ilist[iv];

        for (int kt = 0; kt <= i; kt += 32) {
            // load up to 32 k-rows of Hb (float4-coalesced)
            for (int l = tid; l < 32 * 32; l += 256) {
                int r = l >> 5, e4 = (l & 31) << 2;
                int k = kt + r;
                float4 v = make_float4(0.f, 0.f, 0.f, 0.f);
                if (k <= i)
                    v = *(const float4*)&g_Hb[((b * T_ + i) * T_ + k) * E_ + e4];
                *(float4*)&hb_s[r][e4] = v;
            }
            __syncthreads();

            const int kb = kt + wrp * 4;   // this warp's 4 k-rows
            if (kb <= i) {
                float d[4][4];
#pragma unroll
                for (int t = 0; t < 4; t++)
#pragma unroll
                    for (int g = 0; g < 4; g++) d[t][g] = 0.f;
                const float* __restrict__ wb = wsb + (lane << 2);
                const int r0 = wrp * 4;
#pragma unroll 4
                for (int kk = 0; kk < E_; kk++) {
                    float4 wv = *(const float4*)(wb + kk * 128);
                    float h0 = hb_s[r0][kk];
                    float h1 = hb_s[r0 + 1][kk];
                    float h2 = hb_s[r0 + 2][kk];
                    float h3 = hb_s[r0 + 3][kk];
                    d[0][0] += h0 * wv.x; d[0][1] += h0 * wv.y; d[0][2] += h0 * wv.z; d[0][3] += h0 * wv.w;
                    d[1][0] += h1 * wv.x; d[1][1] += h1 * wv.y; d[1][2] += h1 * wv.z; d[1][3] += h1 * wv.w;
                    d[2][0] += h2 * wv.x; d[2][1] += h2 * wv.y; d[2][2] += h2 * wv.z; d[2][3] += h2 * wv.w;
                    d[3][0] += h3 * wv.x; d[3][1] += h3 * wv.y; d[3][2] += h3 * wv.z; d[3][3] += h3 * wv.w;
                }
#pragma unroll
                for (int t = 0; t < 4; t++) {
                    const int k = kb + t;
                    if (k <= i) {
                        const int j = i - k;
                        const float* ep = g_emb + (b * T_ + j) * E_ + lane;
                        float u = fast_tanh(d[t][0] + s_bbe[lane])      * ep[0]  * s_wout[lane]
                                + fast_tanh(d[t][1] + s_bbe[lane + 32]) * ep[32] * s_wout[lane + 32]
                                + fast_tanh(d[t][2] + s_bbe[lane + 64]) * ep[64] * s_wout[lane + 64]
                                + fast_tanh(d[t][3] + s_bbe[lane + 96]) * ep[96] * s_wout[lane + 96];
#pragma unroll
                        for (int o = 16; o; o >>= 1)
                            u += __shfl_xor_sync(0xffffffffu, u, o);
                        if (lane == 0) u_s[k] = u;
                    }
                }
            }
            __syncthreads();
        }

        if (wrp == 0) {   // softmax over k = 0..i and output
            const float* sp = g_S + (b * T_ + i) * T_;
            float s0 = (lane <= i)      ? sp[lane]      : -INFINITY;
            float s1 = (lane + 32 <= i) ? sp[lane + 32] : -INFINITY;
            float mx = fmaxf(s0, s1);
#pragma unroll
            for (int o = 16; o; o >>= 1)
                mx = fmaxf(mx, __shfl_xor_sync(0xffffffffu, mx, o));
            float e0 = (lane <= i)      ? __expf(s0 - mx) : 0.f;
            float e1 = (lane + 32 <= i) ? __expf(s1 - mx) : 0.f;
            float num = e0 * ((lane <= i)      ? u_s[lane]      : 0.f)
                      + e1 * ((lane + 32 <= i) ? u_s[lane + 32] : 0.f);
            float den = e0 + e1;
#pragma unroll
            for (int o = 16; o; o >>= 1) {
                num += __shfl_xor_sync(0xffffffffu, num, o);
                den += __shfl_xor_sync(0xffffffffu, den, o);
            }
            if (lane == 0) {
                float valid = (i < lengths[b]) ? 1.f : 0.f;
                out[b * T_ + i] = (num / den) * valid + b_out[0];
            }
        }
        __syncthreads();
    }
}

// ---------------- launch ----------------
extern "C" void kernel_launch(void* const* d_in, const int* in_sizes, int n_in,
                              void* d_out, int out_size) {
    const float* x       = (const float*)d_in[0];
    const float* tt      = (const float*)d_in[1];
    const int*   lengths = (const int*)  d_in[2];
    const float* Wemb    = (const float*)d_in[3];
    const float* Wih_a   = (const float*)d_in[4];
    const float* Whh_a   = (const float*)d_in[5];
    const float* bih_a   = (const float*)d_in[6];
    const float* bhh_a   = (const float*)d_in[7];
    const float* Wih_b   = (const float*)d_in[8];
    const float* Whh_b   = (const float*)d_in[9];
    const float* bih_b   = (const float*)d_in[10];
    const float* bhh_b   = (const float*)d_in[11];
    const float* w_alpha = (const float*)d_in[12];
    const float* b_alpha = (const float*)d_in[13];
    const float* W_beta  = (const float*)d_in[14];
    const float* b_beta  = (const float*)d_in[15];
    const float* W_out   = (const float*)d_in[16];
    const float* b_out   = (const float*)d_in[17];
    float* out = (float*)d_out;

    cudaFuncSetAttribute(k_gru, cudaFuncAttributeMaxDynamicSharedMemorySize,
                         GRU_SMEM);
    cudaFuncSetAttribute(k_attn, cudaFuncAttributeMaxDynamicSharedMemorySize,
                         ATTN_SMEM);

    k_prep<<<1088, 256>>>(W_beta);
    k_embed<<<dim3(64, 2), 256>>>(x, Wemb);
    k_gi<<<dim3(64, 12), 256>>>(tt, Wih_a, Wih_b, bih_a, bih_b, bhh_a, bhh_b);
    k_gru<<<128, 256, GRU_SMEM>>>(Whh_a, Whh_b, bhh_a, bhh_b, w_alpha, b_alpha);
    k_attn<<<512, 256, ATTN_SMEM>>>(b_beta, W_out, b_out, lengths, out);
}